// round 17
// baseline (speedup 1.0000x reference)
#include <cuda_runtime.h>
#include <cuda_fp16.h>
#include <cstdint>

#define H 256
#define G 128                 // z grid points per time slice
#define NT 9                  // distinct RK4 stage times
#define NE (NT * G)           // 1152 table entries
#define TILE_E 8              // evals per CTA
#define NCTA 144              // == NE / TILE_E ; <= 148 SMs, co-resident
#define MARGIN 3.0f
#define M2 296                // final knot count

// ---- persistent scratch ----
__device__ unsigned long long g_barC;        // monotonic barrier counter (never reset)
__device__ float2 g_red[NCTA];               // per-CTA minmax partials
__device__ __half2 g_w2h[32768];             // W2 as fp16 pairs
__device__ float2 g_tab[NE];                 // (f, g) per (time, zgrid)

// smem offsets (bytes)
#define W2S_OFF 0                      // 32768 half2 = 128 KB (phase 1)
#define HG_OFF  131072                 // rows pitch 80B; k>=128 half shifted +64B
#define HG_BYTES 20544
#define PART_OFF (HG_OFF + HG_BYTES)   // part[32][4][2] float2 = 2048
#define RED_OFF  (PART_OFF + 2048)     // float2 red[144] = 1152
#define SMEM_TOTAL (RED_OFF + 1216)
// phase-2 aliases (over the dead W2 region):
#define STAB_OFF 0                     // NE float2 = 9216
#define SZF_OFF  9216                  // M2 floats
#define SP_OFF   (SZF_OFF + 1184)
#define SDV_OFF  (SP_OFF + 1184)

__device__ __forceinline__ float fast_tanh(float x) {
    float e, r;
    asm("ex2.approx.f32 %0, %1;" : "=f"(e) : "f"(x * 2.8853900817779268f));
    asm("rcp.approx.f32 %0, %1;" : "=f"(r) : "f"(e + 1.0f));
    return 1.0f - 2.0f * r;
}
__device__ __forceinline__ void fma2(unsigned long long &acc,
                                     unsigned long long hv,
                                     unsigned long long w2) {
    asm("fma.rn.f32x2 %0, %1, %2, %0;" : "+l"(acc) : "l"(hv), "l"(w2));
}
__device__ __forceinline__ float acc_lo(unsigned long long a) {
    return __uint_as_float((unsigned)(a & 0xffffffffULL));
}
__device__ __forceinline__ float acc_hi(unsigned long long a) {
    return __uint_as_float((unsigned)(a >> 32));
}

// device-wide barrier: monotonic counter, reset-free across launches/replays.
__device__ __forceinline__ void grid_barrier() {
    __syncthreads();
    if (threadIdx.x == 0) {
        __threadfence();                               // release my writes
        unsigned long long old = atomicAdd(&g_barC, 1ULL);
        unsigned long long tgt = (old / NCTA) * NCTA + NCTA;
        const volatile unsigned long long* pc = &g_barC;
        while (*pc < tgt) __nanosleep(64);
        __threadfence();                               // acquire others' writes
    }
    __syncthreads();
}

// stage lookup: Hermite on f (exact slope g), Catmull-Rom on g
__device__ __forceinline__ void stage_lookup(
    const float2* stab, int ti, float zin,
    float lot, float invdz, float dzv, float &fv, float &gv)
{
    float u = (zin - lot) * invdz;
    int i0 = (int)u;
    i0 = max(1, min(i0, G - 3));
    float sf = u - (float)i0;
    const float2* row = stab + ti * G;
    float2 m1 = row[i0 - 1];
    float2 p0 = row[i0];
    float2 p1 = row[i0 + 1];
    float2 p2 = row[i0 + 2];
    float om  = 1.f - sf;
    float h00 = (1.f + 2.f * sf) * om * om;
    float h10 = sf * om * om;
    float h01 = sf * sf * (3.f - 2.f * sf);
    float h11 = sf * sf * (sf - 1.f);
    fv = h00 * p0.x + h10 * (p0.y * dzv) + h01 * p1.x + h11 * (p1.y * dzv);
    float sl0 = 0.5f * (p1.y - m1.y);
    float sl1 = 0.5f * (p2.y - p0.y);
    gv = h00 * p0.y + h10 * sl0 + h01 * p1.y + h11 * sl1;
}

// ---------------- the fused kernel: prep | table | chain+interp ----------------
__global__ void __launch_bounds__(1024) fused_kernel(
    const float* __restrict__ z0, int B,
    const float* __restrict__ W1, const float* __restrict__ b1v,
    const float* __restrict__ W2, const float* __restrict__ b2v,
    const float* __restrict__ W3, const float* __restrict__ b3v,
    float* __restrict__ out)
{
    extern __shared__ __align__(16) char smem_raw[];
    char* hgb = smem_raw + HG_OFF;
    float2 (*part)[4][2] = reinterpret_cast<float2(*)[4][2]>(smem_raw + PART_OFF);
    float2* red = reinterpret_cast<float2*>(smem_raw + RED_OFF);

    const int tid  = threadIdx.x;
    const int lane = tid & 31;
    const int wrp  = tid >> 5;
    const int fp   = tid >> 3;
    const int grp  = (tid >> 1) & 3;
    const int ks   = tid & 1;
    const int jA   = tid & 255;
    const int q    = tid >> 8;

    // ================= phase 0: distributed prep (balanced across CTAs) =================
    {
        // W2 -> fp16: 16384 float4 spread 114/CTA
        const int wper = (16384 + NCTA - 1) / NCTA;      // 114
        int wi = blockIdx.x * wper + tid;
        if (tid < wper && wi < 16384) {
            float4 w = reinterpret_cast<const float4*>(W2)[wi];
            g_w2h[2 * wi]     = __float22half2_rn(make_float2(w.x, w.y));
            g_w2h[2 * wi + 1] = __float22half2_rn(make_float2(w.z, w.w));
        }
        // z0 minmax partial, spread across CTAs
        float lo = 1e30f, hi = -1e30f;
        const int n4 = B >> 2;
        const int zper = (n4 + NCTA - 1) / NCTA;
        int zi = blockIdx.x * zper + tid;
        if (tid < zper && zi < n4) {
            float4 v = reinterpret_cast<const float4*>(z0)[zi];
            lo = fminf(fminf(v.x, v.y), fminf(v.z, v.w));
            hi = fmaxf(fmaxf(v.x, v.y), fmaxf(v.z, v.w));
        }
        // fp32 tail (B not divisible by 4): CTA 0, thread 0
        if (blockIdx.x == 0 && tid == 0) {
            for (int i = n4 << 2; i < B; ++i) {
                float v = z0[i];
                lo = fminf(lo, v);
                hi = fmaxf(hi, v);
            }
        }
        #pragma unroll
        for (int off = 16; off > 0; off >>= 1) {
            lo = fminf(lo, __shfl_xor_sync(0xffffffffu, lo, off));
            hi = fmaxf(hi, __shfl_xor_sync(0xffffffffu, hi, off));
        }
        if (lane == 0) red[wrp] = make_float2(lo, hi);
        __syncthreads();
        if (tid < 32) {
            float2 r = red[tid];
            lo = r.x; hi = r.y;
            #pragma unroll
            for (int off = 16; off > 0; off >>= 1) {
                lo = fminf(lo, __shfl_xor_sync(0xffffffffu, lo, off));
                hi = fmaxf(hi, __shfl_xor_sync(0xffffffffu, hi, off));
            }
            if (tid == 0) g_red[blockIdx.x] = make_float2(lo, hi);
        }
    }
    grid_barrier();

    // ================= phase 1: stage-field table =================
    // stage W2 fp16 from global, rotated +4 column-pairs for k-half 1
    for (int lin = tid; lin < 8192; lin += 1024) {
        int k  = lin >> 5;
        int c4 = (lin & 31) << 2;
        uint4 v = *reinterpret_cast<const uint4*>(&g_w2h[k * 128 + c4]);
        int cr = (c4 + 4 * (k >> 7)) & 127;
        *reinterpret_cast<uint4*>(smem_raw + (size_t)(k * 128 + cr) * 4) = v;
    }
    // reduce the 144 minmax partials
    if (tid < NCTA) red[tid] = g_red[tid];
    __syncthreads();
    if (tid < 32) {
        float lo = red[tid].x, hi = red[tid].y;
        #pragma unroll
        for (int j = 1; j < 4; ++j) {
            float2 r = red[tid + 32 * j];
            lo = fminf(lo, r.x);
            hi = fmaxf(hi, r.y);
        }
        if (tid < 16) {
            float2 r = red[tid + 128];
            lo = fminf(lo, r.x);
            hi = fmaxf(hi, r.y);
        }
        #pragma unroll
        for (int off = 16; off > 0; off >>= 1) {
            lo = fminf(lo, __shfl_xor_sync(0xffffffffu, lo, off));
            hi = fmaxf(hi, __shfl_xor_sync(0xffffffffu, hi, off));
        }
        if (tid == 0) red[0] = make_float2(lo, hi);
    }
    __syncthreads();

    const float lo0 = red[0].x, hi0 = red[0].y;
    const float lot = lo0 - MARGIN;
    const float dz  = (hi0 + MARGIN - lot) / (float)(G - 1);
    const float invdz = 1.0f / dz;

    // phase A: layer 1 (rank-1) + JVP, 2 evals per thread
    {
        const float a  = W1[jA];
        const float tw = W1[H + jA];
        const float b1 = b1v[jA];
        char* rowp = hgb + jA * 80 + (jA >> 7) * 64 + q * 16;
        #pragma unroll
        for (int e = 0; e < 2; ++e) {
            int id = blockIdx.x * TILE_E + 2 * q + e;
            int ti = id >> 7;
            int zi = id & 127;
            float t  = 0.125f * (float)ti;
            float zv = lot + (float)zi * dz;
            float h = fast_tanh(fmaf(zv, a, fmaf(t, tw, b1)));
            float g = (1.f - h * h) * a;
            *reinterpret_cast<float2*>(rowp + 8 * e) = make_float2(h, g);
        }
    }
    __syncthreads();

    // phase B: dual GEMM, register double-buffered (batch 4 loads, then FMA)
    unsigned long long a0[2] = {0, 0};
    unsigned long long a1[2] = {0, 0};
    {
        const char* wb = smem_raw + ks * 65536 + ((fp + 4 * ks) & 127) * 4;
        const char* hb = hgb + ks * (128 * 80 + 64) + grp * 16;
        #pragma unroll 4
        for (int kb = 0; kb < 128; kb += 4) {
            uint32_t w4[4];
            ulonglong2 v4[4];
            #pragma unroll
            for (int u = 0; u < 4; ++u) {
                w4[u] = *reinterpret_cast<const uint32_t*>(wb + (size_t)(kb + u) * 512);
                v4[u] = *reinterpret_cast<const ulonglong2*>(hb + (size_t)(kb + u) * 80);
            }
            #pragma unroll
            for (int u = 0; u < 4; ++u) {
                float2 wf = __half22float2(*reinterpret_cast<__half2*>(&w4[u]));
                unsigned long long w0, w1;
                asm("mov.b64 %0, {%1, %1};" : "=l"(w0) : "f"(wf.x));
                asm("mov.b64 %0, {%1, %1};" : "=l"(w1) : "f"(wf.y));
                fma2(a0[0], v4[u].x, w0); fma2(a0[1], v4[u].y, w0);
                fma2(a1[0], v4[u].x, w1); fma2(a1[1], v4[u].y, w1);
            }
        }
    }

    // merge k-halves (lane bit 0); lane parity keeps its own feature
    float m[8];
    #pragma unroll
    for (int e = 0; e < 2; ++e) {
        m[2 * e]         = acc_lo(a0[e]);
        m[2 * e + 1]     = acc_hi(a0[e]);
        m[4 + 2 * e]     = acc_lo(a1[e]);
        m[4 + 2 * e + 1] = acc_hi(a1[e]);
    }
    #pragma unroll
    for (int v = 0; v < 8; ++v)
        m[v] += __shfl_xor_sync(0xffffffffu, m[v], 1);

    // epilogue: layer-2 tanh + JVP, project W3, reduce over features
    {
        const int jm = 2 * fp + ks;
        const float b2m = b2v[jm];
        const float w3m = W3[jm];
        #pragma unroll
        for (int e = 0; e < 2; ++e) {
            float ph = ks ? m[4 + 2 * e] : m[2 * e];
            float pg = ks ? m[5 + 2 * e] : m[2 * e + 1];
            float h2 = fast_tanh(ph + b2m);
            float cf = h2 * w3m;
            float cg = (1.f - h2 * h2) * pg * w3m;
            cf += __shfl_xor_sync(0xffffffffu, cf, 1);
            cg += __shfl_xor_sync(0xffffffffu, cg, 1);
            cf += __shfl_xor_sync(0xffffffffu, cf, 8);
            cg += __shfl_xor_sync(0xffffffffu, cg, 8);
            cf += __shfl_xor_sync(0xffffffffu, cf, 16);
            cg += __shfl_xor_sync(0xffffffffu, cg, 16);
            if ((lane & 25) == 0)
                part[wrp][lane >> 1][e] = make_float2(cf, cg);
        }
    }
    __syncthreads();

    if (tid < TILE_E) {
        const int gq = tid >> 1, eq = tid & 1;
        float f = b3v[0], g = 0.f;
        #pragma unroll
        for (int w = 0; w < 32; ++w) {
            float2 p = part[w][gq][eq];
            f += p.x;
            g += p.y;
        }
        g_tab[blockIdx.x * TILE_E + tid] = make_float2(f, g);
    }
    grid_barrier();

    // ================= phase 2: knot chain + per-sample interp =================
    float2* stab = reinterpret_cast<float2*>(smem_raw + STAB_OFF);
    float*  szf  = reinterpret_cast<float*>(smem_raw + SZF_OFF);
    float*  sp   = reinterpret_cast<float*>(smem_raw + SP_OFF);
    float*  sdv  = reinterpret_cast<float*>(smem_raw + SDV_OFF);

    for (int i = tid; i < NE; i += 1024) stab[i] = g_tab[i];
    __syncthreads();

    const float span  = fmaxf(hi0 - lo0, 1e-9f);
    const float kstep = span / (float)(M2 - 1);
    const float dt    = 0.25f;

    if (tid < M2) {
        float z = lo0 + (float)tid * kstep;
        float p = 1.f, dv = 0.f, zin = z, pin = 1.f;
        #pragma unroll 1
        for (int st = 0; st < 4; ++st) {
            float az = 0.f, ad = 0.f, ap = 0.f;
            #pragma unroll
            for (int s = 0; s < 4; ++s) {
                const int ti = 2 * st + ((s == 0) ? 0 : ((s == 3) ? 2 : 1));
                float fv, gv;
                stage_lookup(stab, ti, zin, lot, invdz, dz, fv, gv);
                float kp = gv * pin;
                const float wgt = (s == 1 || s == 2) ? 2.f : 1.f;
                az += wgt * fv;
                ad += wgt * gv;
                ap += wgt * kp;
                if (s < 3) {
                    const float cn = (s == 2) ? dt : (0.5f * dt);
                    zin = fmaf(cn, fv, z);
                    pin = fmaf(cn, kp, p);
                } else {
                    z  = fmaf(dt / 6.0f, az, z);
                    p  = fmaf(dt / 6.0f, ap, p);
                    dv = fmaf(dt / 6.0f, ad, dv);
                    zin = z;
                    pin = p;
                }
            }
        }
        szf[tid] = z;
        sp [tid] = p;
        sdv[tid] = dv;
    }
    __syncthreads();

    // interp: this CTA owns a contiguous block of samples
    const int per = (B + NCTA - 1) / NCTA;
    const int base = blockIdx.x * per;
    const float inv = (float)(M2 - 1) / span;
    for (int k = tid; k < per; k += 1024) {
        int i = base + k;
        if (i >= B) break;
        float u = (z0[i] - lo0) * inv;
        u = fminf(fmaxf(u, 0.f), (float)(M2 - 1));
        int ii = min((int)u, M2 - 2);
        float s = u - (float)ii;

        float om  = 1.f - s;
        float h00 = (1.f + 2.f * s) * om * om;
        float h10 = s * om * om;
        float h01 = s * s * (3.f - 2.f * s);
        float h11 = s * s * (s - 1.f);

        float zf_i = szf[ii], zf_j = szf[ii + 1];
        float p_i  = sp[ii]  * kstep, p_j = sp[ii + 1] * kstep;
        float zf   = h00 * zf_i + h10 * p_i + h01 * zf_j + h11 * p_j;

        float dv_i = sdv[ii], dv_j = sdv[ii + 1];
        float sl_i = (ii > 0) ? 0.5f * (dv_j - sdv[ii - 1]) : (dv_j - dv_i);
        float sl_j = (ii + 2 < M2) ? 0.5f * (sdv[ii + 2] - dv_i) : (dv_j - dv_i);
        float dvv  = h00 * dv_i + h10 * sl_i + h01 * dv_j + h11 * sl_j;

        out[i]     = zf;
        out[B + i] = dvv;
    }
}

extern "C" void kernel_launch(void* const* d_in, const int* in_sizes, int n_in,
                              void* d_out, int out_size) {
    const float* z0 = (const float*)d_in[0];
    const float* W1 = (const float*)d_in[1];
    const float* b1 = (const float*)d_in[2];
    const float* W2 = (const float*)d_in[3];
    const float* b2 = (const float*)d_in[4];
    const float* W3 = (const float*)d_in[5];
    const float* b3 = (const float*)d_in[6];
    float* out = (float*)d_out;
    const int B = in_sizes[0];

    cudaFuncSetAttribute(fused_kernel,
                         cudaFuncAttributeMaxDynamicSharedMemorySize, SMEM_TOTAL);

    fused_kernel<<<NCTA, 1024, SMEM_TOTAL>>>(z0, B, W1, b1, W2, b2, W3, b3, out);
}